// round 4
// baseline (speedup 1.0000x reference)
#include <cuda_runtime.h>
#include <cuda_fp16.h>
#include <cstdint>
#include <cstddef>

// ================= problem =================
// x:(16,128,112,112)f32  weight:(128,128,3,3)  P:(2,128,128,3,3)  bias:(128)
// out:(16,128,112,112) = conv(x, scatter(weight,P) 9x9, pad 4) + bias

#define TAPS 81

// K2 as f16, layout [tap][co][ci]  (256 B per co row)
__device__ uint4 g_K2h4[TAPS * 2048];

__device__ __forceinline__ uint32_t smem_u32(const void* p) {
    uint32_t a;
    asm("{ .reg .u64 t; cvta.to.shared.u64 t, %1; cvt.u32.u64 %0, t; }" : "=r"(a) : "l"(p));
    return a;
}

#define LDSM4(rv, addr)                                                          \
    asm volatile("ldmatrix.sync.aligned.m8n8.x4.shared.b16 {%0,%1,%2,%3}, [%4];" \
        : "=r"((rv)[0]), "=r"((rv)[1]), "=r"((rv)[2]), "=r"((rv)[3]) : "r"(addr))

#define HMMA(d, a, b0, b1)                                                   \
    asm volatile("mma.sync.aligned.m16n8k16.row.col.f32.f16.f16.f32 "        \
        "{%0,%1,%2,%3}, {%4,%5,%6,%7}, {%8,%9}, {%0,%1,%2,%3};"              \
        : "+f"((d)[0]), "+f"((d)[1]), "+f"((d)[2]), "+f"((d)[3])             \
        : "r"((a)[0]), "r"((a)[1]), "r"((a)[2]), "r"((a)[3]),                \
          "r"(b0), "r"(b1))

#define CP_ASYNC16(sdst, gsrc)                                               \
    asm volatile("cp.async.cg.shared.global [%0], [%1], 16;"                 \
        :: "r"(sdst), "l"(gsrc) : "memory")
#define CP_COMMIT()   asm volatile("cp.async.commit_group;" ::: "memory")
#define CP_WAIT3()    asm volatile("cp.async.wait_group 3;" ::: "memory")

// ================= stage 1: scatter weights -> f16 K2 =================
__global__ void build_K(const float* __restrict__ weight, const float* __restrict__ P) {
    __shared__ float sK[128][81];
    const int co = blockIdx.x;
    const int ci = threadIdx.x;

    #pragma unroll
    for (int i = 0; i < 81; i++) sK[ci][i] = 0.f;

    const float* P0 = P;
    const float* P1 = P + 128 * 128 * 9;

    #pragma unroll
    for (int kh = 0; kh < 3; kh++) {
        #pragma unroll
        for (int kw = 0; kw < 3; kw++) {
            int widx = ((co * 128 + ci) * 3 + kh) * 3 + kw;
            float w  = weight[widx];
            float ph = (float)(kh * 4) + P0[widx];
            float pw = (float)(kw * 4) + P1[widx];
            ph = fminf(fmaxf(ph, 0.f), 8.f);
            pw = fminf(fmaxf(pw, 0.f), 8.f);
            float fh = floorf(ph), fw = floorf(pw);
            float rh = ph - fh,    rw = pw - fw;
            int ih = (int)fh, iw = (int)fw;
            int ih1 = min(ih + 1, 8), iw1 = min(iw + 1, 8);
            sK[ci][ih  * 9 + iw ] += w * (1.f - rh) * (1.f - rw);
            sK[ci][ih1 * 9 + iw ] += w * rh         * (1.f - rw);
            sK[ci][ih  * 9 + iw1] += w * (1.f - rh) * rw;
            sK[ci][ih1 * 9 + iw1] += w * rh         * rw;
        }
    }
    __syncwarp();
    __half* g = (__half*)g_K2h4;
    for (int tap = 0; tap < 81; tap++)
        g[((size_t)tap * 128 + co) * 128 + ci] = __float2half_rn(sK[ci][tap]);
}

// ================= stage 2: fp16 implicit-GEMM conv =================
// Block: 64 co x (4 rows x 112 w) = 448 px. 8 warps = 2 co-halves x 4 rows.
// Warp tile: 32 co x 112 px = 2 m-frags x 14 n-frags, acc 112 regs.
// K = ci in 4 chunks of 32. x tile (12 rows x 120 cols, halo) staged per chunk,
// shared by all 81 taps as pure address offsets.
// A (K2 slice, 32co x 32ci per warp) is WARP-PRIVATE: each warp cp.asyncs its
// own slice into a private 4-stage ring -> no block barriers in the tap loop.
#define XS_STRIDE 80
#define XS_BYTES  (1440 * XS_STRIDE)          // 12*120 pix rows      = 115200
#define A_STAGE   2560                        // 32 co rows * 80 B
#define A_OFF     XS_BYTES
#define SMEM_TOTAL (A_OFF + 8 * 4 * A_STAGE)  // 197120

__global__ __launch_bounds__(256, 1)
void dcls_mma(const float* __restrict__ x, const float* __restrict__ bias,
              float* __restrict__ out) {
    extern __shared__ char smem[];
    const uint32_t sb = smem_u32(smem);

    const int tid  = threadIdx.x;
    const int lane = tid & 31;
    const int warp = tid >> 5;
    const int h    = warp & 1;       // co half within block
    const int r    = warp >> 1;      // output row 0..3

    const int s  = blockIdx.x;       // 0..895
    const int ch = s & 1;
    const int hg = (s >> 1) % 28;
    const int bb = s / 56;
    const int h0 = hg * 4;
    const int co0 = ch * 64;

    // warp-private A ring base
    const uint32_t warpA = sb + A_OFF + warp * (4 * A_STAGE);
    // cp.async per-lane offsets: chunk k covers co_l = (lane>>2)+8k, seg = lane&3
    const int cp_col = (lane >> 2);
    const int cp_seg = (lane & 3) * 16;

    // ldmatrix lane offsets
    const uint32_t a_lane = (uint32_t)((lane & 15) * XS_STRIDE + (lane >> 4) * 16);
    const int bnrow = (lane & 7) + ((lane >> 4) << 3);
    const uint32_t b_lane = (uint32_t)(bnrow * XS_STRIDE + ((lane >> 3) & 1) * 16);

    float acc[2][14][4];
    #pragma unroll
    for (int i = 0; i < 2; i++)
        #pragma unroll
        for (int j = 0; j < 14; j++)
            #pragma unroll
            for (int k = 0; k < 4; k++) acc[i][j][k] = 0.f;

    const char* gK2 = (const char*)g_K2h4;

    for (int c = 0; c < 4; c++) {
        const int ci0 = c * 32;
        __syncthreads();   // all warps done reading previous chunk's xs

        // ---- stage x tile: 12 rows x 120 cols x 32 ci (half2 pairs) ----
        {
            const float* xb = x + (size_t)(bb * 128 + ci0) * 12544;
            for (int u = tid; u < 23040; u += 256) {
                int cp = u & 15;          // ci pair
                int p  = u >> 4;          // pixel 0..1439
                int hh = p / 120, wp = p - hh * 120;
                int gh = h0 - 4 + hh, gw = wp - 4;
                float v0 = 0.f, v1 = 0.f;
                if ((unsigned)gh < 112u && (unsigned)gw < 112u) {
                    const float* px = xb + (size_t)(2 * cp) * 12544 + gh * 112 + gw;
                    v0 = px[0];
                    v1 = px[12544];
                }
                *(__half2*)(smem + p * XS_STRIDE + cp * 4) = __floats2half2_rn(v0, v1);
            }
        }
        __syncthreads();

        // ---- per-warp A-slice global base for this chunk ----
        const char* gA = gK2 + (size_t)(co0 + h * 32) * 256 + (size_t)ci0 * 2;

        // prologue: stages for taps 0..2
        #pragma unroll
        for (int t = 0; t < 3; t++) {
            const char* g = gA + (size_t)t * 32768;
            uint32_t sdst = warpA + t * A_STAGE;
            #pragma unroll
            for (int k = 0; k < 4; k++)
                CP_ASYNC16(sdst + (cp_col + 8 * k) * XS_STRIDE + cp_seg,
                           g + (cp_col + 8 * k) * 256 + cp_seg);
            CP_COMMIT();
        }

        for (int tap = 0; tap < 81; tap++) {
            // keep the ring full: stage tap+3 (its buffer was last read at tap-1)
            if (tap + 3 <= 80) {
                const char* g = gA + (size_t)(tap + 3) * 32768;
                uint32_t sdst = warpA + ((tap + 3) & 3) * A_STAGE;
                #pragma unroll
                for (int k = 0; k < 4; k++)
                    CP_ASYNC16(sdst + (cp_col + 8 * k) * XS_STRIDE + cp_seg,
                               g + (cp_col + 8 * k) * 256 + cp_seg);
            }
            CP_COMMIT();        // commit every iter (possibly empty) to keep counts uniform
            CP_WAIT3();         // stage `tap` complete
            __syncwarp();       // publish cp.async writes across the warp

            const int dh = tap / 9, dw = tap - dh * 9;
            const uint32_t abase = warpA + (tap & 3) * A_STAGE + a_lane;
            const uint32_t bbase = sb + (uint32_t)(((r + dh) * 120 + dw) * XS_STRIDE) + b_lane;

            #pragma unroll
            for (int kk = 0; kk < 2; kk++) {
                uint32_t a[2][4];
                LDSM4(a[0], abase + kk * 32);
                LDSM4(a[1], abase + 1280 + kk * 32);
                #pragma unroll
                for (int j2 = 0; j2 < 7; j2++) {
                    uint32_t b[4];
                    LDSM4(b, bbase + j2 * 1280 + kk * 32);
                    HMMA(acc[0][2 * j2],     a[0], b[0], b[1]);
                    HMMA(acc[0][2 * j2 + 1], a[0], b[2], b[3]);
                    HMMA(acc[1][2 * j2],     a[1], b[0], b[1]);
                    HMMA(acc[1][2 * j2 + 1], a[1], b[2], b[3]);
                }
            }
        }
    }

    // ================= epilogue: + bias, float2 stores =================
    const int gq = lane >> 2, tq = lane & 3;
    #pragma unroll
    for (int i = 0; i < 2; i++) {
        const int co = co0 + h * 32 + i * 16 + gq;
        const float b0 = bias[co];
        const float b1 = bias[co + 8];
        const size_t o0 = ((size_t)(bb * 128 + co) * 112 + (h0 + r)) * 112;
        const size_t o1 = o0 + (size_t)8 * 12544;
        #pragma unroll
        for (int j = 0; j < 14; j++) {
            const int wcol = j * 8 + tq * 2;
            *(float2*)(out + o0 + wcol) = make_float2(acc[i][j][0] + b0, acc[i][j][1] + b0);
            *(float2*)(out + o1 + wcol) = make_float2(acc[i][j][2] + b1, acc[i][j][3] + b1);
        }
    }
}

// ================= launch =================
extern "C" void kernel_launch(void* const* d_in, const int* in_sizes, int n_in,
                              void* d_out, int out_size) {
    const float* x      = (const float*)d_in[0];
    const float* weight = (const float*)d_in[1];
    const float* P      = (const float*)d_in[2];
    const float* bias   = (const float*)d_in[3];
    float* out = (float*)d_out;

    build_K<<<128, 128>>>(weight, P);

    cudaFuncSetAttribute(dcls_mma, cudaFuncAttributeMaxDynamicSharedMemorySize, SMEM_TOTAL);
    dcls_mma<<<896, 256, SMEM_TOTAL>>>(x, bias, out);
}

// round 6
// speedup vs baseline: 1.2452x; 1.2452x over previous
#include <cuda_runtime.h>
#include <cuda_fp16.h>
#include <cstdint>
#include <cstddef>

// ================= problem =================
// x:(16,128,112,112)f32  weight:(128,128,3,3)  P:(2,128,128,3,3)  bias:(128)
// out:(16,128,112,112) = conv(x, scatter(weight,P) 9x9, pad 4) + bias

#define TAPS 81

// K2 in MMA *fragment layout*: [tap][cichunk(4)][cotile16(8)][kk(2)][lane(32)] uint4.
// Lane's uint4 = {a0,a1,a2,a3} of one m16k16 fp16 A-tile:
//   a0=(row,col01) a1=(row+8,col01) a2=(row,col89) a3=(row+8,col89)
//   row: co within 16-tile, col: ci within 16-tile, lane=(row&7)*4+((col&7)>>1)
__device__ uint4 g_K2f[TAPS * 4 * 8 * 2 * 32];

__device__ __forceinline__ uint32_t smem_u32(const void* p) {
    uint32_t a;
    asm("{ .reg .u64 t; cvta.to.shared.u64 t, %1; cvt.u32.u64 %0, t; }" : "=r"(a) : "l"(p));
    return a;
}

#define LDSM4(rv, addr)                                                          \
    asm volatile("ldmatrix.sync.aligned.m8n8.x4.shared.b16 {%0,%1,%2,%3}, [%4];" \
        : "=r"((rv)[0]), "=r"((rv)[1]), "=r"((rv)[2]), "=r"((rv)[3]) : "r"(addr))

#define LDSM2(rv, addr)                                                      \
    asm volatile("ldmatrix.sync.aligned.m8n8.x2.shared.b16 {%0,%1}, [%2];"   \
        : "=r"((rv)[0]), "=r"((rv)[1]) : "r"(addr))

#define HMMA(d, a, b0, b1)                                                   \
    asm volatile("mma.sync.aligned.m16n8k16.row.col.f32.f16.f16.f32 "        \
        "{%0,%1,%2,%3}, {%4,%5,%6,%7}, {%8,%9}, {%0,%1,%2,%3};"              \
        : "+f"((d)[0]), "+f"((d)[1]), "+f"((d)[2]), "+f"((d)[3])             \
        : "r"((a)[0]), "r"((a)[1]), "r"((a)[2]), "r"((a)[3]),                \
          "r"(b0), "r"(b1))

// ================= stage 1: scatter weights -> fragment-layout f16 K2 =================
// block = co (128), thread = ci (128); each thread owns a private 81-row.
__global__ void build_K(const float* __restrict__ weight, const float* __restrict__ P) {
    __shared__ float sK[128][81];
    const int co = blockIdx.x;
    const int ci = threadIdx.x;

    #pragma unroll
    for (int i = 0; i < 81; i++) sK[ci][i] = 0.f;

    const float* P0 = P;
    const float* P1 = P + 128 * 128 * 9;

    #pragma unroll
    for (int kh = 0; kh < 3; kh++) {
        #pragma unroll
        for (int kw = 0; kw < 3; kw++) {
            int widx = ((co * 128 + ci) * 3 + kh) * 3 + kw;
            float w  = weight[widx];
            float ph = (float)(kh * 4) + P0[widx];
            float pw = (float)(kw * 4) + P1[widx];
            ph = fminf(fmaxf(ph, 0.f), 8.f);
            pw = fminf(fmaxf(pw, 0.f), 8.f);
            float fh = floorf(ph), fw = floorf(pw);
            float rh = ph - fh,    rw = pw - fw;
            int ih = (int)fh, iw = (int)fw;
            int ih1 = min(ih + 1, 8), iw1 = min(iw + 1, 8);
            sK[ci][ih  * 9 + iw ] += w * (1.f - rh) * (1.f - rw);
            sK[ci][ih1 * 9 + iw ] += w * rh         * (1.f - rw);
            sK[ci][ih  * 9 + iw1] += w * (1.f - rh) * rw;
            sK[ci][ih1 * 9 + iw1] += w * rh         * rw;
        }
    }
    __syncwarp();

    // (co,ci) -> fragment slot
    const int c     = ci >> 5;
    const int kk    = (ci >> 4) & 1;
    const int col   = ci & 15;
    const int iglob = co >> 4;
    const int row   = co & 15;
    const int lane  = (row & 7) * 4 + ((col & 7) >> 1);
    const int reg   = (row >> 3) + ((col >> 3) << 1);
    __half* gh = (__half*)g_K2f;
    const size_t slot = ((((size_t)c * 8 + iglob) * 2 + kk) * 32 + lane) * 8 + reg * 2 + (col & 1);
    for (int tap = 0; tap < 81; tap++)
        gh[(size_t)tap * 16384 + slot] = __float2half_rn(sK[ci][tap]);   // 2048 uint4/tap = 16384 halves
}

// ================= stage 2: fp16 implicit-GEMM conv =================
// Block: 128 co x (4 rows x 56 w). 8 warps = 2 co-halves(64) x 4 rows.
// Warp tile: 64co x 56px = 4 m-frags x 7 n-frags, acc 112 regs.
// A (K2) comes straight from global in fragment layout: 8x LDG.128 per warp
// per tap, register double-buffered; warps sharing a co-half hit L1.
// B (x tile) from smem via ldmatrix; x staged per 32-ci chunk, 81 taps reuse
// it as pure address offsets. No block barriers inside the tap loop.
#define XS_STRIDE 80
#define SMEM_TOTAL (768 * XS_STRIDE)      // 12 rows x 64 cols pixels -> 61440 B

__global__ __launch_bounds__(256, 1)
void dcls_mma(const float* __restrict__ x, const float* __restrict__ bias,
              float* __restrict__ out) {
    extern __shared__ char smem[];
    const uint32_t sb = smem_u32(smem);

    const int tid  = threadIdx.x;
    const int lane = tid & 31;
    const int warp = tid >> 5;
    const int h    = warp & 1;       // co half (64) within block
    const int r    = warp >> 1;      // output row 0..3

    const int s  = blockIdx.x;       // 0..895
    const int wt = s & 1;
    const int hg = (s >> 1) % 28;
    const int bb = s / 56;
    const int h0 = hg * 4;
    const int w0 = wt * 56;

    // ldmatrix B lane offset
    const int bnrow = (lane & 7) + ((lane >> 4) << 3);
    const uint32_t b_lane = (uint32_t)(bnrow * XS_STRIDE + ((lane >> 3) & 1) * 16);

    float acc[4][7][4];
    #pragma unroll
    for (int i = 0; i < 4; i++)
        #pragma unroll
        for (int j = 0; j < 7; j++)
            #pragma unroll
            for (int k = 0; k < 4; k++) acc[i][j][k] = 0.f;

    for (int c = 0; c < 4; c++) {
        __syncthreads();   // all warps done reading previous chunk's xs

        // ---- stage x tile: 12 rows x 64 cols x 32 ci, f16, zero-padded halo ----
        {
            const float* xb = x + (size_t)(bb * 128 + c * 32) * 12544;
            #pragma unroll
            for (int q = 0; q < 3; q++) {
                const int p  = tid + q * 256;          // pixel 0..767
                const int hh = p >> 6, wp = p & 63;
                const int gh_ = h0 - 4 + hh, gw = w0 - 4 + wp;
                const bool ok = ((unsigned)gh_ < 112u) & ((unsigned)gw < 112u);
                const float* px = xb + gh_ * 112 + gw;
                char* sdst = smem + p * XS_STRIDE;
                #pragma unroll
                for (int cp = 0; cp < 16; cp++) {
                    float v0 = 0.f, v1 = 0.f;
                    if (ok) {
                        v0 = px[(size_t)(2 * cp) * 12544];
                        v1 = px[(size_t)(2 * cp + 1) * 12544];
                    }
                    *(__half2*)(sdst + cp * 4) = __floats2half2_rn(v0, v1);
                }
            }
        }
        __syncthreads();

        // per-(tap,c,warp) A base: 16 tiles per (tap,c); this warp uses 8 of them
        const uint4* Ab = g_K2f + ((size_t)c * 16 + h * 8) * 32 + lane;

        uint4 cur[8], nxt[8];
        #pragma unroll
        for (int t = 0; t < 8; t++) cur[t] = Ab[t * 32];   // tap 0

        for (int tap = 0; tap < 81; tap++) {
            if (tap < 80) {
                const uint4* An = Ab + (size_t)(tap + 1) * 2048;
                #pragma unroll
                for (int t = 0; t < 8; t++) nxt[t] = An[t * 32];
            }

            const int dh = tap / 9, dw = tap - dh * 9;
            const uint32_t bbase = sb + (uint32_t)(((r + dh) * 64 + dw) * XS_STRIDE) + b_lane;

            #pragma unroll
            for (int kk = 0; kk < 2; kk++) {
                #pragma unroll
                for (int j2 = 0; j2 < 3; j2++) {
                    uint32_t b[4];
                    LDSM4(b, bbase + j2 * 1280 + kk * 32);
                    #pragma unroll
                    for (int i = 0; i < 4; i++) {
                        const uint32_t* a = reinterpret_cast<const uint32_t*>(&cur[i * 2 + kk]);
                        HMMA(acc[i][2 * j2],     a, b[0], b[1]);
                        HMMA(acc[i][2 * j2 + 1], a, b[2], b[3]);
                    }
                }
                uint32_t b2[2];
                LDSM2(b2, bbase + 3 * 1280 + kk * 32);
                #pragma unroll
                for (int i = 0; i < 4; i++) {
                    const uint32_t* a = reinterpret_cast<const uint32_t*>(&cur[i * 2 + kk]);
                    HMMA(acc[i][6], a, b2[0], b2[1]);
                }
            }

            if (tap < 80) {
                #pragma unroll
                for (int t = 0; t < 8; t++) cur[t] = nxt[t];
            }
        }
    }

    // ================= epilogue: + bias, float2 stores =================
    const int gq = lane >> 2, tq = lane & 3;
    #pragma unroll
    for (int i = 0; i < 4; i++) {
        const int co = h * 64 + i * 16 + gq;
        const float b0 = bias[co];
        const float b1 = bias[co + 8];
        const size_t o0 = ((size_t)(bb * 128 + co) * 112 + (h0 + r)) * 112 + w0;
        const size_t o1 = o0 + (size_t)8 * 12544;
        #pragma unroll
        for (int j = 0; j < 7; j++) {
            const int wcol = j * 8 + tq * 2;
            *(float2*)(out + o0 + wcol) = make_float2(acc[i][j][0] + b0, acc[i][j][1] + b0);
            *(float2*)(out + o1 + wcol) = make_float2(acc[i][j][2] + b1, acc[i][j][3] + b1);
        }
    }
}

// ================= launch =================
extern "C" void kernel_launch(void* const* d_in, const int* in_sizes, int n_in,
                              void* d_out, int out_size) {
    const float* x      = (const float*)d_in[0];
    const float* weight = (const float*)d_in[1];
    const float* P      = (const float*)d_in[2];
    const float* bias   = (const float*)d_in[3];
    float* out = (float*)d_out;

    build_K<<<128, 128>>>(weight, P);

    cudaFuncSetAttribute(dcls_mma, cudaFuncAttributeMaxDynamicSharedMemorySize, SMEM_TOTAL);
    dcls_mma<<<896, 256, SMEM_TOTAL>>>(x, bias, out);
}